// round 6
// baseline (speedup 1.0000x reference)
#include <cuda_runtime.h>
#include <cuda_fp16.h>
#include <cstdint>

#define N_NODES_MAX 100000
#define N_EDGES_MAX 1600000
#define FDIM 128
#define SCAN_BS 512

// ---------------- scratch (no allocs allowed) ----------------
__device__ __half g_xt[(size_t)N_NODES_MAX * FDIM];   // GEMM output, fp16
__device__ float  g_h1[(size_t)N_NODES_MAX * FDIM];   // layer-1 output, fp32
__device__ float  g_dinv[N_NODES_MAX];
__device__ int    g_cnt[N_NODES_MAX];
__device__ int    g_rowptr[N_NODES_MAX];
__device__ int    g_cur[N_NODES_MAX];
__device__ int    g_src_sorted[N_EDGES_MAX];
__device__ int    g_bsums[512];

// ---------------- histogram + dinv ----------------
__global__ void cnt_zero_kernel(int* cnt, int n) {
    int i = blockIdx.x * blockDim.x + threadIdx.x;
    if (i < n) cnt[i] = 0;
}

__global__ void hist_kernel(const int* __restrict__ cols, int* cnt, int E) {
    int i = blockIdx.x * blockDim.x + threadIdx.x;
    int stride = gridDim.x * blockDim.x;
    int E4 = E >> 2;
    const int4* c4 = (const int4*)cols;
    for (int e = i; e < E4; e += stride) {
        int4 v = c4[e];
        atomicAdd(&cnt[v.x], 1);
        atomicAdd(&cnt[v.y], 1);
        atomicAdd(&cnt[v.z], 1);
        atomicAdd(&cnt[v.w], 1);
    }
    for (int e = E4 * 4 + i; e < E; e += stride) atomicAdd(&cnt[cols[e]], 1);
}

__global__ void dinv_kernel(const int* __restrict__ cnt, float* dinv, int n) {
    int i = blockIdx.x * blockDim.x + threadIdx.x;
    if (i < n) dinv[i] = rsqrtf((float)cnt[i] + 1.0f);
}

// ---------------- exclusive scan (3 kernels) ----------------
__global__ void scan_block_kernel(const int* __restrict__ cnt, int* scanout,
                                  int* bsums, int n) {
    __shared__ int sh[SCAN_BS];
    int gid = blockIdx.x * SCAN_BS + threadIdx.x;
    int v = (gid < n) ? cnt[gid] : 0;
    sh[threadIdx.x] = v;
    __syncthreads();
    for (int off = 1; off < SCAN_BS; off <<= 1) {
        int t = (threadIdx.x >= off) ? sh[threadIdx.x - off] : 0;
        __syncthreads();
        sh[threadIdx.x] += t;
        __syncthreads();
    }
    if (gid < n) scanout[gid] = sh[threadIdx.x] - v;
    if (threadIdx.x == SCAN_BS - 1) bsums[blockIdx.x] = sh[threadIdx.x];
}

__global__ void scan_sums_kernel(int* bsums, int nb) {
    __shared__ int sh[SCAN_BS];
    int v = (threadIdx.x < nb) ? bsums[threadIdx.x] : 0;
    sh[threadIdx.x] = v;
    __syncthreads();
    for (int off = 1; off < SCAN_BS; off <<= 1) {
        int t = (threadIdx.x >= off) ? sh[threadIdx.x - off] : 0;
        __syncthreads();
        sh[threadIdx.x] += t;
        __syncthreads();
    }
    if (threadIdx.x < nb) bsums[threadIdx.x] = sh[threadIdx.x] - v;
}

__global__ void scan_add_cursor_kernel(int* scanout, const int* __restrict__ bsums,
                                       int* cur, int n) {
    int gid = blockIdx.x * SCAN_BS + threadIdx.x;
    if (gid < n) {
        int v = scanout[gid] + bsums[blockIdx.x];
        scanout[gid] = v;
        cur[gid] = v;
    }
}

// ---------------- edge placement (counting sort by dst) ----------------
__global__ void place_kernel(const int* __restrict__ rows, const int* __restrict__ cols,
                             int* cur, int* __restrict__ srcs, int E) {
    int i = blockIdx.x * blockDim.x + threadIdx.x;
    int stride = gridDim.x * blockDim.x;
    int E4 = E >> 2;
    const int4* r4 = (const int4*)rows;
    const int4* c4 = (const int4*)cols;
    for (int e = i; e < E4; e += stride) {
        int4 c = c4[e];
        int4 r = r4[e];
        srcs[atomicAdd(&cur[c.x], 1)] = r.x;
        srcs[atomicAdd(&cur[c.y], 1)] = r.y;
        srcs[atomicAdd(&cur[c.z], 1)] = r.z;
        srcs[atomicAdd(&cur[c.w], 1)] = r.w;
    }
    for (int e = E4 * 4 + i; e < E; e += stride)
        srcs[atomicAdd(&cur[cols[e]], 1)] = rows[e];
}

// ---------------- tf32 tensor-core GEMM: out_h[N,128] = x[N,128] @ W[128,128] ----
#define MT 128
#define KB 32

__device__ __forceinline__ uint32_t f2tf32(float f) {
    uint32_t u;
    asm("cvt.rna.tf32.f32 %0, %1;" : "=r"(u) : "f"(f));
    return u;
}

__global__ __launch_bounds__(256, 2) void gemm_tc_kernel(
    const float* __restrict__ x, const float* __restrict__ W,
    __half* __restrict__ out, int nrows)
{
    __shared__ uint32_t xs[MT][KB + 4];     // tf32; stride 36 -> conflict-free frags
    __shared__ uint32_t ws[KB][FDIM + 8];   // tf32; stride 136 -> conflict-free frags

    int tid = threadIdx.x;
    int wid = tid >> 5;
    int lane = tid & 31;
    int m_base = (wid & 3) * 32;
    int n_base = (wid >> 2) * 64;
    int row0 = blockIdx.x * MT;

    float acc[2][8][4];
#pragma unroll
    for (int im = 0; im < 2; im++)
#pragma unroll
        for (int in = 0; in < 8; in++)
#pragma unroll
            for (int j = 0; j < 4; j++) acc[im][in][j] = 0.0f;

    int lr = tid >> 3;
    int lk = (tid & 7) * 4;
    int wk = tid >> 5;
    int wc = (tid & 31) * 4;

    for (int k0 = 0; k0 < FDIM; k0 += KB) {
#pragma unroll
        for (int p = 0; p < 4; p++) {
            int r = lr + p * 32;
            float4 v = make_float4(0.f, 0.f, 0.f, 0.f);
            if (row0 + r < nrows)
                v = *(const float4*)(x + (long long)(row0 + r) * FDIM + k0 + lk);
            xs[r][lk]     = f2tf32(v.x);
            xs[r][lk + 1] = f2tf32(v.y);
            xs[r][lk + 2] = f2tf32(v.z);
            xs[r][lk + 3] = f2tf32(v.w);
        }
#pragma unroll
        for (int p = 0; p < 4; p++) {
            int kk = wk + p * 8;
            float4 v = *(const float4*)(W + (long long)(k0 + kk) * FDIM + wc);
            ws[kk][wc]     = f2tf32(v.x);
            ws[kk][wc + 1] = f2tf32(v.y);
            ws[kk][wc + 2] = f2tf32(v.z);
            ws[kk][wc + 3] = f2tf32(v.w);
        }
        __syncthreads();

#pragma unroll
        for (int ks = 0; ks < KB / 8; ks++) {
            int kk = ks * 8;
            uint32_t a[2][4];
            int ac = kk + (lane & 3);
#pragma unroll
            for (int im = 0; im < 2; im++) {
                int r0 = m_base + im * 16 + (lane >> 2);
                a[im][0] = xs[r0][ac];
                a[im][1] = xs[r0 + 8][ac];
                a[im][2] = xs[r0][ac + 4];
                a[im][3] = xs[r0 + 8][ac + 4];
            }
#pragma unroll
            for (int in = 0; in < 8; in++) {
                int c = n_base + in * 8 + (lane >> 2);
                uint32_t b0 = ws[kk + (lane & 3)][c];
                uint32_t b1 = ws[kk + 4 + (lane & 3)][c];
#pragma unroll
                for (int im = 0; im < 2; im++) {
                    asm volatile(
                        "mma.sync.aligned.m16n8k8.row.col.f32.tf32.tf32.f32 "
                        "{%0,%1,%2,%3}, {%4,%5,%6,%7}, {%8,%9}, {%0,%1,%2,%3};"
                        : "+f"(acc[im][in][0]), "+f"(acc[im][in][1]),
                          "+f"(acc[im][in][2]), "+f"(acc[im][in][3])
                        : "r"(a[im][0]), "r"(a[im][1]), "r"(a[im][2]), "r"(a[im][3]),
                          "r"(b0), "r"(b1));
                }
            }
        }
        __syncthreads();
    }

    // epilogue -> fp16
#pragma unroll
    for (int im = 0; im < 2; im++) {
        int r = row0 + m_base + im * 16 + (lane >> 2);
#pragma unroll
        for (int in = 0; in < 8; in++) {
            int c = n_base + in * 8 + 2 * (lane & 3);
            if (r < nrows)
                *(__half2*)(out + (long long)r * FDIM + c) =
                    __floats2half2_rn(acc[im][in][0], acc[im][in][1]);
            if (r + 8 < nrows)
                *(__half2*)(out + (long long)(r + 8) * FDIM + c) =
                    __floats2half2_rn(acc[im][in][2], acc[im][in][3]);
        }
    }
}

// ---------------- aggregate: warp per node, shuffle-batched edge indices ------
__global__ __launch_bounds__(256) void aggregate_kernel(
    const __half* __restrict__ xt, const int* __restrict__ rowptr,
    const int* __restrict__ cnt, const int* __restrict__ srcs,
    const float* __restrict__ dinv, const float* __restrict__ b,
    float* __restrict__ out, int n)
{
    int warp = (blockIdx.x * blockDim.x + threadIdx.x) >> 5;
    int lane = threadIdx.x & 31;
    if (warp >= n) return;

    float dc = __ldg(dinv + warp);
    float4 bb = *(const float4*)(b + lane * 4);
    uint2 sraw = *(const uint2*)(xt + (long long)warp * FDIM + lane * 4);
    float2 s01 = __half22float2(*(__half2*)&sraw.x);
    float2 s23 = __half22float2(*(__half2*)&sraw.y);
    float self = dc * dc;
    float4 acc;
    acc.x = fmaf(s01.x, self, bb.x);
    acc.y = fmaf(s01.y, self, bb.y);
    acc.z = fmaf(s23.x, self, bb.z);
    acc.w = fmaf(s23.y, self, bb.w);

    int k0 = __ldg(rowptr + warp);
    int deg = __ldg(cnt + warp);

    for (int base = 0; base < deg; base += 32) {
        int m = deg - base;
        if (m > 32) m = 32;
        // coalesced batch load of up to 32 edge indices + their dinv (parallel)
        int s_my = 0;
        float n_my = 0.0f;
        if (lane < m) {
            s_my = __ldg(srcs + k0 + base + lane);
            n_my = dc * __ldg(dinv + s_my);
        }
        // broadcast each edge to all lanes; gathers are independent -> deep MLP
#pragma unroll 8
        for (int j = 0; j < m; j++) {
            int sj = __shfl_sync(0xffffffffu, s_my, j);
            float nj = __shfl_sync(0xffffffffu, n_my, j);
            uint2 v = *(const uint2*)(xt + (long long)sj * FDIM + lane * 4);
            float2 v01 = __half22float2(*(__half2*)&v.x);
            float2 v23 = __half22float2(*(__half2*)&v.y);
            acc.x = fmaf(v01.x, nj, acc.x);
            acc.y = fmaf(v01.y, nj, acc.y);
            acc.z = fmaf(v23.x, nj, acc.z);
            acc.w = fmaf(v23.y, nj, acc.w);
        }
    }
    *(float4*)(out + (long long)warp * FDIM + lane * 4) = acc;
}

// ---------------- launch ----------------
extern "C" void kernel_launch(void* const* d_in, const int* in_sizes, int n_in,
                              void* d_out, int out_size)
{
    const float* node_feature = (const float*)d_in[0];
    const int*   edge_index   = (const int*)d_in[1];   // int32 (jax x64 disabled)
    const float* W1 = (const float*)d_in[2];
    const float* b1 = (const float*)d_in[3];
    const float* W2 = (const float*)d_in[4];
    const float* b2 = (const float*)d_in[5];
    float* out = (float*)d_out;

    int n = in_sizes[0] / FDIM;          // 100000
    int E = in_sizes[1] / 2;             // 1600000
    const int* rows = edge_index;
    const int* cols = edge_index + E;

    __half* xt;
    float *h1, *dinv;
    int *cnt, *rowptr, *cur, *srcs, *bsums;
    cudaGetSymbolAddress((void**)&xt,     g_xt);
    cudaGetSymbolAddress((void**)&h1,     g_h1);
    cudaGetSymbolAddress((void**)&dinv,   g_dinv);
    cudaGetSymbolAddress((void**)&cnt,    g_cnt);
    cudaGetSymbolAddress((void**)&rowptr, g_rowptr);
    cudaGetSymbolAddress((void**)&cur,    g_cur);
    cudaGetSymbolAddress((void**)&srcs,   g_src_sorted);
    cudaGetSymbolAddress((void**)&bsums,  g_bsums);

    int tb = 256;
    int nb_nodes = (n + tb - 1) / tb;
    int nb_edge4 = ((E >> 2) + tb - 1) / tb;
    int nb_gemm  = (n + MT - 1) / MT;
    int nb_scan  = (n + SCAN_BS - 1) / SCAN_BS;
    int nb_agg   = (n * 32 + tb - 1) / tb;

    // CSR build (shared by both layers)
    cnt_zero_kernel<<<nb_nodes, tb>>>(cnt, n);
    hist_kernel<<<nb_edge4, tb>>>(cols, cnt, E);
    dinv_kernel<<<nb_nodes, tb>>>(cnt, dinv, n);
    scan_block_kernel<<<nb_scan, SCAN_BS>>>(cnt, rowptr, bsums, n);
    scan_sums_kernel<<<1, SCAN_BS>>>(bsums, nb_scan);
    scan_add_cursor_kernel<<<nb_scan, SCAN_BS>>>(rowptr, bsums, cur, n);
    place_kernel<<<nb_edge4, tb>>>(rows, cols, cur, srcs, E);

    // layer 1
    gemm_tc_kernel<<<nb_gemm, tb>>>(node_feature, W1, xt, n);
    aggregate_kernel<<<nb_agg, tb>>>(xt, rowptr, cnt, srcs, dinv, b1, h1, n);

    // layer 2
    gemm_tc_kernel<<<nb_gemm, tb>>>(h1, W2, xt, n);
    aggregate_kernel<<<nb_agg, tb>>>(xt, rowptr, cnt, srcs, dinv, b2, out, n);
}

// round 7
// speedup vs baseline: 1.0728x; 1.0728x over previous
#include <cuda_runtime.h>
#include <cuda_fp16.h>
#include <cstdint>

#define N_NODES_MAX 100000
#define N_EDGES_MAX 1600000
#define FDIM 128
#define SCAN_BS 512

// ---------------- scratch (no allocs allowed) ----------------
__device__ __half g_xt[(size_t)N_NODES_MAX * FDIM];   // GEMM output, fp16
__device__ float  g_h1[(size_t)N_NODES_MAX * FDIM];   // layer-1 output, fp32
__device__ float  g_dinv[N_NODES_MAX];
__device__ int    g_cnt[N_NODES_MAX];
__device__ int    g_rowptr[N_NODES_MAX];
__device__ int    g_cur[N_NODES_MAX];
__device__ int2   g_epair[N_EDGES_MAX];               // {src, bitcast(dinv[src])} grouped by dst
__device__ int    g_bsums[512];

// ---------------- histogram + dinv ----------------
__global__ void cnt_zero_kernel(int* cnt, int n) {
    int i = blockIdx.x * blockDim.x + threadIdx.x;
    if (i < n) cnt[i] = 0;
}

__global__ void hist_kernel(const int* __restrict__ cols, int* cnt, int E) {
    int i = blockIdx.x * blockDim.x + threadIdx.x;
    int stride = gridDim.x * blockDim.x;
    int E4 = E >> 2;
    const int4* c4 = (const int4*)cols;
    for (int e = i; e < E4; e += stride) {
        int4 v = c4[e];
        atomicAdd(&cnt[v.x], 1);
        atomicAdd(&cnt[v.y], 1);
        atomicAdd(&cnt[v.z], 1);
        atomicAdd(&cnt[v.w], 1);
    }
    for (int e = E4 * 4 + i; e < E; e += stride) atomicAdd(&cnt[cols[e]], 1);
}

__global__ void dinv_kernel(const int* __restrict__ cnt, float* dinv, int n) {
    int i = blockIdx.x * blockDim.x + threadIdx.x;
    if (i < n) dinv[i] = rsqrtf((float)cnt[i] + 1.0f);
}

// ---------------- exclusive scan (3 kernels) ----------------
__global__ void scan_block_kernel(const int* __restrict__ cnt, int* scanout,
                                  int* bsums, int n) {
    __shared__ int sh[SCAN_BS];
    int gid = blockIdx.x * SCAN_BS + threadIdx.x;
    int v = (gid < n) ? cnt[gid] : 0;
    sh[threadIdx.x] = v;
    __syncthreads();
    for (int off = 1; off < SCAN_BS; off <<= 1) {
        int t = (threadIdx.x >= off) ? sh[threadIdx.x - off] : 0;
        __syncthreads();
        sh[threadIdx.x] += t;
        __syncthreads();
    }
    if (gid < n) scanout[gid] = sh[threadIdx.x] - v;
    if (threadIdx.x == SCAN_BS - 1) bsums[blockIdx.x] = sh[threadIdx.x];
}

__global__ void scan_sums_kernel(int* bsums, int nb) {
    __shared__ int sh[SCAN_BS];
    int v = (threadIdx.x < nb) ? bsums[threadIdx.x] : 0;
    sh[threadIdx.x] = v;
    __syncthreads();
    for (int off = 1; off < SCAN_BS; off <<= 1) {
        int t = (threadIdx.x >= off) ? sh[threadIdx.x - off] : 0;
        __syncthreads();
        sh[threadIdx.x] += t;
        __syncthreads();
    }
    if (threadIdx.x < nb) bsums[threadIdx.x] = sh[threadIdx.x] - v;
}

__global__ void scan_add_cursor_kernel(int* scanout, const int* __restrict__ bsums,
                                       int* cur, int n) {
    int gid = blockIdx.x * SCAN_BS + threadIdx.x;
    if (gid < n) {
        int v = scanout[gid] + bsums[blockIdx.x];
        scanout[gid] = v;
        cur[gid] = v;
    }
}

// ---------------- edge placement: counting sort by dst, pack (src, dinv[src]) ---
__global__ void place_kernel(const int* __restrict__ rows, const int* __restrict__ cols,
                             const float* __restrict__ dinv,
                             int* cur, int2* __restrict__ epair, int E) {
    int i = blockIdx.x * blockDim.x + threadIdx.x;
    int stride = gridDim.x * blockDim.x;
    int E4 = E >> 2;
    const int4* r4 = (const int4*)rows;
    const int4* c4 = (const int4*)cols;
    for (int e = i; e < E4; e += stride) {
        int4 c = c4[e];
        int4 r = r4[e];
        epair[atomicAdd(&cur[c.x], 1)] = make_int2(r.x, __float_as_int(__ldg(dinv + r.x)));
        epair[atomicAdd(&cur[c.y], 1)] = make_int2(r.y, __float_as_int(__ldg(dinv + r.y)));
        epair[atomicAdd(&cur[c.z], 1)] = make_int2(r.z, __float_as_int(__ldg(dinv + r.z)));
        epair[atomicAdd(&cur[c.w], 1)] = make_int2(r.w, __float_as_int(__ldg(dinv + r.w)));
    }
    for (int e = E4 * 4 + i; e < E; e += stride) {
        int r = rows[e];
        epair[atomicAdd(&cur[cols[e]], 1)] = make_int2(r, __float_as_int(__ldg(dinv + r)));
    }
}

// ---------------- tf32 tensor-core GEMM: out_h[N,128] = x[N,128] @ W[128,128] ----
#define MT 128
#define KB 32

__device__ __forceinline__ uint32_t f2tf32(float f) {
    uint32_t u;
    asm("cvt.rna.tf32.f32 %0, %1;" : "=r"(u) : "f"(f));
    return u;
}

__global__ __launch_bounds__(256, 2) void gemm_tc_kernel(
    const float* __restrict__ x, const float* __restrict__ W,
    __half* __restrict__ out, int nrows)
{
    __shared__ uint32_t xs[MT][KB + 4];     // tf32; stride 36 -> conflict-free frags
    __shared__ uint32_t ws[KB][FDIM + 8];   // tf32; stride 136 -> conflict-free frags

    int tid = threadIdx.x;
    int wid = tid >> 5;
    int lane = tid & 31;
    int m_base = (wid & 3) * 32;
    int n_base = (wid >> 2) * 64;
    int row0 = blockIdx.x * MT;

    float acc[2][8][4];
#pragma unroll
    for (int im = 0; im < 2; im++)
#pragma unroll
        for (int in = 0; in < 8; in++)
#pragma unroll
            for (int j = 0; j < 4; j++) acc[im][in][j] = 0.0f;

    int lr = tid >> 3;
    int lk = (tid & 7) * 4;
    int wk = tid >> 5;
    int wc = (tid & 31) * 4;

    for (int k0 = 0; k0 < FDIM; k0 += KB) {
#pragma unroll
        for (int p = 0; p < 4; p++) {
            int r = lr + p * 32;
            float4 v = make_float4(0.f, 0.f, 0.f, 0.f);
            if (row0 + r < nrows)
                v = *(const float4*)(x + (long long)(row0 + r) * FDIM + k0 + lk);
            xs[r][lk]     = f2tf32(v.x);
            xs[r][lk + 1] = f2tf32(v.y);
            xs[r][lk + 2] = f2tf32(v.z);
            xs[r][lk + 3] = f2tf32(v.w);
        }
#pragma unroll
        for (int p = 0; p < 4; p++) {
            int kk = wk + p * 8;
            float4 v = *(const float4*)(W + (long long)(k0 + kk) * FDIM + wc);
            ws[kk][wc]     = f2tf32(v.x);
            ws[kk][wc + 1] = f2tf32(v.y);
            ws[kk][wc + 2] = f2tf32(v.z);
            ws[kk][wc + 3] = f2tf32(v.w);
        }
        __syncthreads();

#pragma unroll
        for (int ks = 0; ks < KB / 8; ks++) {
            int kk = ks * 8;
            uint32_t a[2][4];
            int ac = kk + (lane & 3);
#pragma unroll
            for (int im = 0; im < 2; im++) {
                int r0 = m_base + im * 16 + (lane >> 2);
                a[im][0] = xs[r0][ac];
                a[im][1] = xs[r0 + 8][ac];
                a[im][2] = xs[r0][ac + 4];
                a[im][3] = xs[r0 + 8][ac + 4];
            }
#pragma unroll
            for (int in = 0; in < 8; in++) {
                int c = n_base + in * 8 + (lane >> 2);
                uint32_t b0 = ws[kk + (lane & 3)][c];
                uint32_t b1 = ws[kk + 4 + (lane & 3)][c];
#pragma unroll
                for (int im = 0; im < 2; im++) {
                    asm volatile(
                        "mma.sync.aligned.m16n8k8.row.col.f32.tf32.tf32.f32 "
                        "{%0,%1,%2,%3}, {%4,%5,%6,%7}, {%8,%9}, {%0,%1,%2,%3};"
                        : "+f"(acc[im][in][0]), "+f"(acc[im][in][1]),
                          "+f"(acc[im][in][2]), "+f"(acc[im][in][3])
                        : "r"(a[im][0]), "r"(a[im][1]), "r"(a[im][2]), "r"(a[im][3]),
                          "r"(b0), "r"(b1));
                }
            }
        }
        __syncthreads();
    }

    // epilogue -> fp16
#pragma unroll
    for (int im = 0; im < 2; im++) {
        int r = row0 + m_base + im * 16 + (lane >> 2);
#pragma unroll
        for (int in = 0; in < 8; in++) {
            int c = n_base + in * 8 + 2 * (lane & 3);
            if (r < nrows)
                *(__half2*)(out + (long long)r * FDIM + c) =
                    __floats2half2_rn(acc[im][in][0], acc[im][in][1]);
            if (r + 8 < nrows)
                *(__half2*)(out + (long long)(r + 8) * FDIM + c) =
                    __floats2half2_rn(acc[im][in][2], acc[im][in][3]);
        }
    }
}

// ---------------- aggregate: warp per node, packed (src,dinv) pairs -----------
__global__ __launch_bounds__(256) void aggregate_kernel(
    const __half* __restrict__ xt, const int* __restrict__ rowptr,
    const int* __restrict__ cnt, const int2* __restrict__ epair,
    const float* __restrict__ dinv, const float* __restrict__ b,
    float* __restrict__ out, int n)
{
    int warp = (blockIdx.x * blockDim.x + threadIdx.x) >> 5;
    int lane = threadIdx.x & 31;
    if (warp >= n) return;

    float dc = __ldg(dinv + warp);
    float4 bb = *(const float4*)(b + lane * 4);
    uint2 sraw = *(const uint2*)(xt + (long long)warp * FDIM + lane * 4);
    float2 s01 = __half22float2(*(__half2*)&sraw.x);
    float2 s23 = __half22float2(*(__half2*)&sraw.y);
    float self = dc * dc;
    float4 acc;
    acc.x = fmaf(s01.x, self, bb.x);
    acc.y = fmaf(s01.y, self, bb.y);
    acc.z = fmaf(s23.x, self, bb.z);
    acc.w = fmaf(s23.y, self, bb.w);

    int k0 = __ldg(rowptr + warp);
    int k1 = k0 + __ldg(cnt + warp);
#pragma unroll 8
    for (int k = k0; k < k1; k++) {
        int2 e = __ldg(epair + k);           // broadcast 8B, chain depth 2
        float nrm = dc * __int_as_float(e.y);
        uint2 v = *(const uint2*)(xt + (long long)e.x * FDIM + lane * 4);
        float2 v01 = __half22float2(*(__half2*)&v.x);
        float2 v23 = __half22float2(*(__half2*)&v.y);
        acc.x = fmaf(v01.x, nrm, acc.x);
        acc.y = fmaf(v01.y, nrm, acc.y);
        acc.z = fmaf(v23.x, nrm, acc.z);
        acc.w = fmaf(v23.y, nrm, acc.w);
    }
    *(float4*)(out + (long long)warp * FDIM + lane * 4) = acc;
}

// ---------------- launch ----------------
extern "C" void kernel_launch(void* const* d_in, const int* in_sizes, int n_in,
                              void* d_out, int out_size)
{
    const float* node_feature = (const float*)d_in[0];
    const int*   edge_index   = (const int*)d_in[1];   // int32 (jax x64 disabled)
    const float* W1 = (const float*)d_in[2];
    const float* b1 = (const float*)d_in[3];
    const float* W2 = (const float*)d_in[4];
    const float* b2 = (const float*)d_in[5];
    float* out = (float*)d_out;

    int n = in_sizes[0] / FDIM;          // 100000
    int E = in_sizes[1] / 2;             // 1600000
    const int* rows = edge_index;
    const int* cols = edge_index + E;

    __half* xt;
    float *h1, *dinv;
    int *cnt, *rowptr, *cur, *bsums;
    int2* epair;
    cudaGetSymbolAddress((void**)&xt,     g_xt);
    cudaGetSymbolAddress((void**)&h1,     g_h1);
    cudaGetSymbolAddress((void**)&dinv,   g_dinv);
    cudaGetSymbolAddress((void**)&cnt,    g_cnt);
    cudaGetSymbolAddress((void**)&rowptr, g_rowptr);
    cudaGetSymbolAddress((void**)&cur,    g_cur);
    cudaGetSymbolAddress((void**)&epair,  g_epair);
    cudaGetSymbolAddress((void**)&bsums,  g_bsums);

    int tb = 256;
    int nb_nodes = (n + tb - 1) / tb;
    int nb_edge4 = ((E >> 2) + tb - 1) / tb;
    int nb_gemm  = (n + MT - 1) / MT;
    int nb_scan  = (n + SCAN_BS - 1) / SCAN_BS;
    int nb_agg   = (n * 32 + tb - 1) / tb;

    // CSR build (shared by both layers)
    cnt_zero_kernel<<<nb_nodes, tb>>>(cnt, n);
    hist_kernel<<<nb_edge4, tb>>>(cols, cnt, E);
    dinv_kernel<<<nb_nodes, tb>>>(cnt, dinv, n);
    scan_block_kernel<<<nb_scan, SCAN_BS>>>(cnt, rowptr, bsums, n);
    scan_sums_kernel<<<1, SCAN_BS>>>(bsums, nb_scan);
    scan_add_cursor_kernel<<<nb_scan, SCAN_BS>>>(rowptr, bsums, cur, n);
    place_kernel<<<nb_edge4, tb>>>(rows, cols, dinv, cur, epair, E);

    // layer 1
    gemm_tc_kernel<<<nb_gemm, tb>>>(node_feature, W1, xt, n);
    aggregate_kernel<<<nb_agg, tb>>>(xt, rowptr, cnt, epair, dinv, b1, h1, n);

    // layer 2
    gemm_tc_kernel<<<nb_gemm, tb>>>(h1, W2, xt, n);
    aggregate_kernel<<<nb_agg, tb>>>(xt, rowptr, cnt, epair, dinv, b2, out, n);
}

// round 8
// speedup vs baseline: 1.0989x; 1.0243x over previous
#include <cuda_runtime.h>
#include <cuda_fp16.h>
#include <cstdint>

#define N_NODES_MAX 100000
#define N_EDGES_MAX 1600000
#define FDIM 128
#define SCAN_BS 512

// ---------------- scratch (no allocs allowed) ----------------
__device__ __half g_xt[(size_t)N_NODES_MAX * FDIM];   // GEMM output, fp16
__device__ float  g_h1[(size_t)N_NODES_MAX * FDIM];   // layer-1 output, fp32
__device__ float  g_dinv[N_NODES_MAX];
__device__ int    g_cnt[N_NODES_MAX];
__device__ int    g_rowptr[N_NODES_MAX];
__device__ int    g_cur[N_NODES_MAX];
__device__ int2   g_epair[N_EDGES_MAX];               // {src, bitcast(dinv[src])} by dst
__device__ int    g_bsums[512];

// ---------------- histogram ----------------
__global__ void cnt_zero_kernel(int* cnt, int n) {
    int i = blockIdx.x * blockDim.x + threadIdx.x;
    if (i < n) cnt[i] = 0;
}

__global__ void hist_kernel(const int* __restrict__ cols, int* cnt, int E) {
    int i = blockIdx.x * blockDim.x + threadIdx.x;
    int stride = gridDim.x * blockDim.x;
    int E4 = E >> 2;
    const int4* c4 = (const int4*)cols;
    for (int e = i; e < E4; e += stride) {
        int4 v = c4[e];
        atomicAdd(&cnt[v.x], 1);
        atomicAdd(&cnt[v.y], 1);
        atomicAdd(&cnt[v.z], 1);
        atomicAdd(&cnt[v.w], 1);
    }
    for (int e = E4 * 4 + i; e < E; e += stride) atomicAdd(&cnt[cols[e]], 1);
}

// ---------------- exclusive scan (3 kernels); dinv fused into pass 1 ----------
__global__ void scan_block_kernel(const int* __restrict__ cnt, int* scanout,
                                  int* bsums, float* __restrict__ dinv, int n) {
    __shared__ int sh[SCAN_BS];
    int gid = blockIdx.x * SCAN_BS + threadIdx.x;
    int v = (gid < n) ? cnt[gid] : 0;
    if (gid < n) dinv[gid] = rsqrtf((float)v + 1.0f);   // fused
    sh[threadIdx.x] = v;
    __syncthreads();
    for (int off = 1; off < SCAN_BS; off <<= 1) {
        int t = (threadIdx.x >= off) ? sh[threadIdx.x - off] : 0;
        __syncthreads();
        sh[threadIdx.x] += t;
        __syncthreads();
    }
    if (gid < n) scanout[gid] = sh[threadIdx.x] - v;
    if (threadIdx.x == SCAN_BS - 1) bsums[blockIdx.x] = sh[threadIdx.x];
}

__global__ void scan_sums_kernel(int* bsums, int nb) {
    __shared__ int sh[SCAN_BS];
    int v = (threadIdx.x < nb) ? bsums[threadIdx.x] : 0;
    sh[threadIdx.x] = v;
    __syncthreads();
    for (int off = 1; off < SCAN_BS; off <<= 1) {
        int t = (threadIdx.x >= off) ? sh[threadIdx.x - off] : 0;
        __syncthreads();
        sh[threadIdx.x] += t;
        __syncthreads();
    }
    if (threadIdx.x < nb) bsums[threadIdx.x] = sh[threadIdx.x] - v;
}

__global__ void scan_add_cursor_kernel(int* scanout, const int* __restrict__ bsums,
                                       int* cur, int n) {
    int gid = blockIdx.x * SCAN_BS + threadIdx.x;
    if (gid < n) {
        int v = scanout[gid] + bsums[blockIdx.x];
        scanout[gid] = v;
        cur[gid] = v;
    }
}

// ---------------- edge placement: counting sort by dst, pack (src, dinv[src]) ---
__global__ void place_kernel(const int* __restrict__ rows, const int* __restrict__ cols,
                             const float* __restrict__ dinv,
                             int* cur, int2* __restrict__ epair, int E) {
    int i = blockIdx.x * blockDim.x + threadIdx.x;
    int stride = gridDim.x * blockDim.x;
    int E4 = E >> 2;
    const int4* r4 = (const int4*)rows;
    const int4* c4 = (const int4*)cols;
    for (int e = i; e < E4; e += stride) {
        int4 c = c4[e];
        int4 r = r4[e];
        epair[atomicAdd(&cur[c.x], 1)] = make_int2(r.x, __float_as_int(__ldg(dinv + r.x)));
        epair[atomicAdd(&cur[c.y], 1)] = make_int2(r.y, __float_as_int(__ldg(dinv + r.y)));
        epair[atomicAdd(&cur[c.z], 1)] = make_int2(r.z, __float_as_int(__ldg(dinv + r.z)));
        epair[atomicAdd(&cur[c.w], 1)] = make_int2(r.w, __float_as_int(__ldg(dinv + r.w)));
    }
    for (int e = E4 * 4 + i; e < E; e += stride) {
        int r = rows[e];
        epair[atomicAdd(&cur[cols[e]], 1)] = make_int2(r, __float_as_int(__ldg(dinv + r)));
    }
}

// ---------------- tf32 tensor-core GEMM: out_h[N,128] = x[N,128] @ W[128,128] ----
#define MT 128
#define KB 32

__device__ __forceinline__ uint32_t f2tf32(float f) {
    uint32_t u;
    asm("cvt.rna.tf32.f32 %0, %1;" : "=r"(u) : "f"(f));
    return u;
}

__global__ __launch_bounds__(256, 2) void gemm_tc_kernel(
    const float* __restrict__ x, const float* __restrict__ W,
    __half* __restrict__ out, int nrows)
{
    __shared__ uint32_t xs[MT][KB + 4];
    __shared__ uint32_t ws[KB][FDIM + 8];

    int tid = threadIdx.x;
    int wid = tid >> 5;
    int lane = tid & 31;
    int m_base = (wid & 3) * 32;
    int n_base = (wid >> 2) * 64;
    int row0 = blockIdx.x * MT;

    float acc[2][8][4];
#pragma unroll
    for (int im = 0; im < 2; im++)
#pragma unroll
        for (int in = 0; in < 8; in++)
#pragma unroll
            for (int j = 0; j < 4; j++) acc[im][in][j] = 0.0f;

    int lr = tid >> 3;
    int lk = (tid & 7) * 4;
    int wk = tid >> 5;
    int wc = (tid & 31) * 4;

    for (int k0 = 0; k0 < FDIM; k0 += KB) {
#pragma unroll
        for (int p = 0; p < 4; p++) {
            int r = lr + p * 32;
            float4 v = make_float4(0.f, 0.f, 0.f, 0.f);
            if (row0 + r < nrows)
                v = *(const float4*)(x + (long long)(row0 + r) * FDIM + k0 + lk);
            xs[r][lk]     = f2tf32(v.x);
            xs[r][lk + 1] = f2tf32(v.y);
            xs[r][lk + 2] = f2tf32(v.z);
            xs[r][lk + 3] = f2tf32(v.w);
        }
#pragma unroll
        for (int p = 0; p < 4; p++) {
            int kk = wk + p * 8;
            float4 v = *(const float4*)(W + (long long)(k0 + kk) * FDIM + wc);
            ws[kk][wc]     = f2tf32(v.x);
            ws[kk][wc + 1] = f2tf32(v.y);
            ws[kk][wc + 2] = f2tf32(v.z);
            ws[kk][wc + 3] = f2tf32(v.w);
        }
        __syncthreads();

#pragma unroll
        for (int ks = 0; ks < KB / 8; ks++) {
            int kk = ks * 8;
            uint32_t a[2][4];
            int ac = kk + (lane & 3);
#pragma unroll
            for (int im = 0; im < 2; im++) {
                int r0 = m_base + im * 16 + (lane >> 2);
                a[im][0] = xs[r0][ac];
                a[im][1] = xs[r0 + 8][ac];
                a[im][2] = xs[r0][ac + 4];
                a[im][3] = xs[r0 + 8][ac + 4];
            }
#pragma unroll
            for (int in = 0; in < 8; in++) {
                int c = n_base + in * 8 + (lane >> 2);
                uint32_t b0 = ws[kk + (lane & 3)][c];
                uint32_t b1 = ws[kk + 4 + (lane & 3)][c];
#pragma unroll
                for (int im = 0; im < 2; im++) {
                    asm volatile(
                        "mma.sync.aligned.m16n8k8.row.col.f32.tf32.tf32.f32 "
                        "{%0,%1,%2,%3}, {%4,%5,%6,%7}, {%8,%9}, {%0,%1,%2,%3};"
                        : "+f"(acc[im][in][0]), "+f"(acc[im][in][1]),
                          "+f"(acc[im][in][2]), "+f"(acc[im][in][3])
                        : "r"(a[im][0]), "r"(a[im][1]), "r"(a[im][2]), "r"(a[im][3]),
                          "r"(b0), "r"(b1));
                }
            }
        }
        __syncthreads();
    }

#pragma unroll
    for (int im = 0; im < 2; im++) {
        int r = row0 + m_base + im * 16 + (lane >> 2);
#pragma unroll
        for (int in = 0; in < 8; in++) {
            int c = n_base + in * 8 + 2 * (lane & 3);
            if (r < nrows)
                *(__half2*)(out + (long long)r * FDIM + c) =
                    __floats2half2_rn(acc[im][in][0], acc[im][in][1]);
            if (r + 8 < nrows)
                *(__half2*)(out + (long long)(r + 8) * FDIM + c) =
                    __floats2half2_rn(acc[im][in][2], acc[im][in][3]);
        }
    }
}

// ---------------- aggregate v3: warp per node, half-warp per edge row ---------
// lane 0-15 handle even edges, 16-31 odd edges; each lane gathers uint4 (16B,
// 8 halves) so one warp LDG.128 moves 512B = 2 full rows.
__global__ __launch_bounds__(256) void aggregate_kernel(
    const __half* __restrict__ xt, const int* __restrict__ rowptr,
    const int* __restrict__ cnt, const int2* __restrict__ epair,
    const float* __restrict__ dinv, const float* __restrict__ b,
    float* __restrict__ out, int n)
{
    int warp = (blockIdx.x * blockDim.x + threadIdx.x) >> 5;
    int lane = threadIdx.x & 31;
    if (warp >= n) return;
    int half_id = lane >> 4;       // 0 or 1
    int sub = lane & 15;           // dim group: handles dims sub*8 .. sub*8+7

    float dc = __ldg(dinv + warp);

    float acc[8];
#pragma unroll
    for (int j = 0; j < 8; j++) acc[j] = 0.0f;

    int k0 = __ldg(rowptr + warp);
    int k1 = k0 + __ldg(cnt + warp);

#pragma unroll 8
    for (int k = k0 + half_id; k < k1; k += 2) {
        int2 e = __ldg(epair + k);
        float nrm = dc * __int_as_float(e.y);
        uint4 v = *(const uint4*)(xt + (long long)e.x * FDIM + sub * 8);
        float2 f0 = __half22float2(*(__half2*)&v.x);
        float2 f1 = __half22float2(*(__half2*)&v.y);
        float2 f2 = __half22float2(*(__half2*)&v.z);
        float2 f3 = __half22float2(*(__half2*)&v.w);
        acc[0] = fmaf(f0.x, nrm, acc[0]);
        acc[1] = fmaf(f0.y, nrm, acc[1]);
        acc[2] = fmaf(f1.x, nrm, acc[2]);
        acc[3] = fmaf(f1.y, nrm, acc[3]);
        acc[4] = fmaf(f2.x, nrm, acc[4]);
        acc[5] = fmaf(f2.y, nrm, acc[5]);
        acc[6] = fmaf(f3.x, nrm, acc[6]);
        acc[7] = fmaf(f3.y, nrm, acc[7]);
    }

    __syncwarp();
#pragma unroll
    for (int j = 0; j < 8; j++)
        acc[j] += __shfl_down_sync(0xffffffffu, acc[j], 16);

    if (half_id == 0) {
        // self-loop + bias, then single write of the output row
        uint4 s = *(const uint4*)(xt + (long long)warp * FDIM + sub * 8);
        float2 s0 = __half22float2(*(__half2*)&s.x);
        float2 s1 = __half22float2(*(__half2*)&s.y);
        float2 s2 = __half22float2(*(__half2*)&s.z);
        float2 s3 = __half22float2(*(__half2*)&s.w);
        float4 b0 = *(const float4*)(b + sub * 8);
        float4 b1 = *(const float4*)(b + sub * 8 + 4);
        float self = dc * dc;
        float4 o0, o1;
        o0.x = fmaf(s0.x, self, acc[0]) + b0.x;
        o0.y = fmaf(s0.y, self, acc[1]) + b0.y;
        o0.z = fmaf(s1.x, self, acc[2]) + b0.z;
        o0.w = fmaf(s1.y, self, acc[3]) + b0.w;
        o1.x = fmaf(s2.x, self, acc[4]) + b1.x;
        o1.y = fmaf(s2.y, self, acc[5]) + b1.y;
        o1.z = fmaf(s3.x, self, acc[6]) + b1.z;
        o1.w = fmaf(s3.y, self, acc[7]) + b1.w;
        *(float4*)(out + (long long)warp * FDIM + sub * 8)     = o0;
        *(float4*)(out + (long long)warp * FDIM + sub * 8 + 4) = o1;
    }
}

// ---------------- launch ----------------
extern "C" void kernel_launch(void* const* d_in, const int* in_sizes, int n_in,
                              void* d_out, int out_size)
{
    const float* node_feature = (const float*)d_in[0];
    const int*   edge_index   = (const int*)d_in[1];   // int32 (jax x64 disabled)
    const float* W1 = (const float*)d_in[2];
    const float* b1 = (const float*)d_in[3];
    const float* W2 = (const float*)d_in[4];
    const float* b2 = (const float*)d_in[5];
    float* out = (float*)d_out;

    int n = in_sizes[0] / FDIM;          // 100000
    int E = in_sizes[1] / 2;             // 1600000
    const int* rows = edge_index;
    const int* cols = edge_index + E;

    __half* xt;
    float *h1, *dinv;
    int *cnt, *rowptr, *cur, *bsums;
    int2* epair;
    cudaGetSymbolAddress((void**)&xt,     g_xt);
    cudaGetSymbolAddress((void**)&h1,     g_h1);
    cudaGetSymbolAddress((void**)&dinv,   g_dinv);
    cudaGetSymbolAddress((void**)&cnt,    g_cnt);
    cudaGetSymbolAddress((void**)&rowptr, g_rowptr);
    cudaGetSymbolAddress((void**)&cur,    g_cur);
    cudaGetSymbolAddress((void**)&epair,  g_epair);
    cudaGetSymbolAddress((void**)&bsums,  g_bsums);

    int tb = 256;
    int nb_nodes = (n + tb - 1) / tb;
    int nb_edge4 = ((E >> 2) + tb - 1) / tb;
    int nb_gemm  = (n + MT - 1) / MT;
    int nb_scan  = (n + SCAN_BS - 1) / SCAN_BS;
    int nb_agg   = (n * 32 + tb - 1) / tb;

    // side stream + events for CSR || GEMM1 overlap. Created per call and not
    // destroyed (destroying a capture-participating stream invalidates capture;
    // kernel_launch runs only a handful of times, leak is bounded & host-side).
    cudaStream_t s_csr;
    cudaEvent_t ev_fork, ev_join;
    cudaStreamCreateWithFlags(&s_csr, cudaStreamNonBlocking);
    cudaEventCreateWithFlags(&ev_fork, cudaEventDisableTiming);
    cudaEventCreateWithFlags(&ev_join, cudaEventDisableTiming);

    // fork side stream off the main (capture) stream
    cudaEventRecord(ev_fork, 0);
    cudaStreamWaitEvent(s_csr, ev_fork, 0);

    // CSR build on side stream
    cnt_zero_kernel<<<nb_nodes, tb, 0, s_csr>>>(cnt, n);
    hist_kernel<<<nb_edge4, tb, 0, s_csr>>>(cols, cnt, E);
    scan_block_kernel<<<nb_scan, SCAN_BS, 0, s_csr>>>(cnt, rowptr, bsums, dinv, n);
    scan_sums_kernel<<<1, SCAN_BS, 0, s_csr>>>(bsums, nb_scan);
    scan_add_cursor_kernel<<<nb_scan, SCAN_BS, 0, s_csr>>>(rowptr, bsums, cur, n);
    place_kernel<<<nb_edge4, tb, 0, s_csr>>>(rows, cols, dinv, cur, epair, E);
    cudaEventRecord(ev_join, s_csr);

    // GEMM-1 on main stream, concurrent with CSR build
    gemm_tc_kernel<<<nb_gemm, tb>>>(node_feature, W1, xt, n);

    // join: aggregate-1 needs both
    cudaStreamWaitEvent(0, ev_join, 0);
    aggregate_kernel<<<nb_agg, tb>>>(xt, rowptr, cnt, epair, dinv, b1, h1, n);

    // layer 2
    gemm_tc_kernel<<<nb_gemm, tb>>>(h1, W2, xt, n);
    aggregate_kernel<<<nb_agg, tb>>>(xt, rowptr, cnt, epair, dinv, b2, out, n);
}

// round 9
// speedup vs baseline: 1.1534x; 1.0496x over previous
#include <cuda_runtime.h>
#include <cuda_fp16.h>
#include <cstdint>

#define N_NODES_MAX 100000
#define N_EDGES_MAX 1600000
#define FDIM 128
#define SCAN_BS 512

// ---------------- scratch (no allocs allowed) ----------------
__device__ __half g_yt[(size_t)N_NODES_MAX * FDIM];   // (xW)*dinv, fp16 (per layer)
__device__ __half g_h1[(size_t)N_NODES_MAX * FDIM];   // layer-1 output, fp16
__device__ float  g_dinv[N_NODES_MAX];
__device__ int    g_cnt[N_NODES_MAX];
__device__ int    g_rowptr[N_NODES_MAX];
__device__ int    g_cur[N_NODES_MAX];
__device__ int    g_srcs[N_EDGES_MAX];                // src ids grouped by dst
__device__ int    g_bsums[512];

// ---------------- histogram + dinv ----------------
__global__ void cnt_zero_kernel(int* cnt, int n) {
    int i = blockIdx.x * blockDim.x + threadIdx.x;
    if (i < n) cnt[i] = 0;
}

__global__ void hist_kernel(const int* __restrict__ cols, int* cnt, int E) {
    int i = blockIdx.x * blockDim.x + threadIdx.x;
    int stride = gridDim.x * blockDim.x;
    int E4 = E >> 2;
    const int4* c4 = (const int4*)cols;
    for (int e = i; e < E4; e += stride) {
        int4 v = c4[e];
        atomicAdd(&cnt[v.x], 1);
        atomicAdd(&cnt[v.y], 1);
        atomicAdd(&cnt[v.z], 1);
        atomicAdd(&cnt[v.w], 1);
    }
    for (int e = E4 * 4 + i; e < E; e += stride) atomicAdd(&cnt[cols[e]], 1);
}

__global__ void dinv_kernel(const int* __restrict__ cnt, float* dinv, int n) {
    int i = blockIdx.x * blockDim.x + threadIdx.x;
    if (i < n) dinv[i] = rsqrtf((float)cnt[i] + 1.0f);
}

// ---------------- exclusive scan (2 kernels) ----------------
__global__ void scan_block_kernel(const int* __restrict__ cnt, int* scanout,
                                  int* bsums, int n) {
    __shared__ int sh[SCAN_BS];
    int gid = blockIdx.x * SCAN_BS + threadIdx.x;
    int v = (gid < n) ? cnt[gid] : 0;
    sh[threadIdx.x] = v;
    __syncthreads();
    for (int off = 1; off < SCAN_BS; off <<= 1) {
        int t = (threadIdx.x >= off) ? sh[threadIdx.x - off] : 0;
        __syncthreads();
        sh[threadIdx.x] += t;
        __syncthreads();
    }
    if (gid < n) scanout[gid] = sh[threadIdx.x] - v;
    if (threadIdx.x == SCAN_BS - 1) bsums[blockIdx.x] = sh[threadIdx.x];
}

// pass 2+3 fused: each block prefix-sums the (<=256) block sums itself
__global__ void scan_add_cursor_kernel(int* scanout, const int* __restrict__ bsums,
                                       int* cur, int n, int nb) {
    __shared__ int sh[256];
    int t = threadIdx.x;
    if (t < 256) sh[t] = (t < nb) ? bsums[t] : 0;
    __syncthreads();
    for (int off = 1; off < 256; off <<= 1) {
        int v = (t < 256 && t >= off) ? sh[t - off] : 0;
        __syncthreads();
        if (t < 256) sh[t] += v;
        __syncthreads();
    }
    int boff = (blockIdx.x == 0) ? 0 : sh[blockIdx.x - 1];
    int gid = blockIdx.x * SCAN_BS + t;
    if (gid < n) {
        int v = scanout[gid] + boff;
        scanout[gid] = v;
        cur[gid] = v;
    }
}

// ---------------- edge placement (counting sort by dst) ----------------
__global__ void place_kernel(const int* __restrict__ rows, const int* __restrict__ cols,
                             int* cur, int* __restrict__ srcs, int E) {
    int i = blockIdx.x * blockDim.x + threadIdx.x;
    int stride = gridDim.x * blockDim.x;
    int E4 = E >> 2;
    const int4* r4 = (const int4*)rows;
    const int4* c4 = (const int4*)cols;
    for (int e = i; e < E4; e += stride) {
        int4 c = c4[e];
        int4 r = r4[e];
        srcs[atomicAdd(&cur[c.x], 1)] = r.x;
        srcs[atomicAdd(&cur[c.y], 1)] = r.y;
        srcs[atomicAdd(&cur[c.z], 1)] = r.z;
        srcs[atomicAdd(&cur[c.w], 1)] = r.w;
    }
    for (int e = E4 * 4 + i; e < E; e += stride)
        srcs[atomicAdd(&cur[cols[e]], 1)] = rows[e];
}

// ---------------- tf32 tensor-core GEMM with dinv-scaled fp16 output ----------
// yt[r,:] = fp16( (x[r,:] @ W) * dinv[r] )
#define MT 128
#define KB 32

__device__ __forceinline__ uint32_t f2tf32(float f) {
    uint32_t u;
    asm("cvt.rna.tf32.f32 %0, %1;" : "=r"(u) : "f"(f));
    return u;
}

// load 4 consecutive input elements as floats (fp32 or fp16 source)
__device__ __forceinline__ void load4f(const float* p, float* o) {
    float4 v = *(const float4*)p;
    o[0] = v.x; o[1] = v.y; o[2] = v.z; o[3] = v.w;
}
__device__ __forceinline__ void load4f(const __half* p, float* o) {
    uint2 v = *(const uint2*)p;
    float2 a = __half22float2(*(__half2*)&v.x);
    float2 b = __half22float2(*(__half2*)&v.y);
    o[0] = a.x; o[1] = a.y; o[2] = b.x; o[3] = b.y;
}

template <typename TIn>
__global__ __launch_bounds__(256, 2) void gemm_tc_kernel(
    const TIn* __restrict__ x, const float* __restrict__ W,
    const float* __restrict__ dinv, __half* __restrict__ out, int nrows)
{
    __shared__ uint32_t xs[MT][KB + 4];     // tf32; conflict-free frags
    __shared__ uint32_t ws[KB][FDIM + 8];

    int tid = threadIdx.x;
    int wid = tid >> 5;
    int lane = tid & 31;
    int m_base = (wid & 3) * 32;
    int n_base = (wid >> 2) * 64;
    int row0 = blockIdx.x * MT;

    float acc[2][8][4];
#pragma unroll
    for (int im = 0; im < 2; im++)
#pragma unroll
        for (int in = 0; in < 8; in++)
#pragma unroll
            for (int j = 0; j < 4; j++) acc[im][in][j] = 0.0f;

    int lr = tid >> 3;
    int lk = (tid & 7) * 4;
    int wk = tid >> 5;
    int wc = (tid & 31) * 4;

    for (int k0 = 0; k0 < FDIM; k0 += KB) {
#pragma unroll
        for (int p = 0; p < 4; p++) {
            int r = lr + p * 32;
            float v[4] = {0.f, 0.f, 0.f, 0.f};
            if (row0 + r < nrows)
                load4f(x + (long long)(row0 + r) * FDIM + k0 + lk, v);
            xs[r][lk]     = f2tf32(v[0]);
            xs[r][lk + 1] = f2tf32(v[1]);
            xs[r][lk + 2] = f2tf32(v[2]);
            xs[r][lk + 3] = f2tf32(v[3]);
        }
#pragma unroll
        for (int p = 0; p < 4; p++) {
            int kk = wk + p * 8;
            float4 v = *(const float4*)(W + (long long)(k0 + kk) * FDIM + wc);
            ws[kk][wc]     = f2tf32(v.x);
            ws[kk][wc + 1] = f2tf32(v.y);
            ws[kk][wc + 2] = f2tf32(v.z);
            ws[kk][wc + 3] = f2tf32(v.w);
        }
        __syncthreads();

#pragma unroll
        for (int ks = 0; ks < KB / 8; ks++) {
            int kk = ks * 8;
            uint32_t a[2][4];
            int ac = kk + (lane & 3);
#pragma unroll
            for (int im = 0; im < 2; im++) {
                int r0 = m_base + im * 16 + (lane >> 2);
                a[im][0] = xs[r0][ac];
                a[im][1] = xs[r0 + 8][ac];
                a[im][2] = xs[r0][ac + 4];
                a[im][3] = xs[r0 + 8][ac + 4];
            }
#pragma unroll
            for (int in = 0; in < 8; in++) {
                int c = n_base + in * 8 + (lane >> 2);
                uint32_t b0 = ws[kk + (lane & 3)][c];
                uint32_t b1 = ws[kk + 4 + (lane & 3)][c];
#pragma unroll
                for (int im = 0; im < 2; im++) {
                    asm volatile(
                        "mma.sync.aligned.m16n8k8.row.col.f32.tf32.tf32.f32 "
                        "{%0,%1,%2,%3}, {%4,%5,%6,%7}, {%8,%9}, {%0,%1,%2,%3};"
                        : "+f"(acc[im][in][0]), "+f"(acc[im][in][1]),
                          "+f"(acc[im][in][2]), "+f"(acc[im][in][3])
                        : "r"(a[im][0]), "r"(a[im][1]), "r"(a[im][2]), "r"(a[im][3]),
                          "r"(b0), "r"(b1));
                }
            }
        }
        __syncthreads();
    }

    // epilogue: scale by dinv[row], convert to fp16
#pragma unroll
    for (int im = 0; im < 2; im++) {
        int r = row0 + m_base + im * 16 + (lane >> 2);
        float d0 = (r < nrows) ? __ldg(dinv + r) : 0.f;
        float d1 = (r + 8 < nrows) ? __ldg(dinv + r + 8) : 0.f;
#pragma unroll
        for (int in = 0; in < 8; in++) {
            int c = n_base + in * 8 + 2 * (lane & 3);
            if (r < nrows)
                *(__half2*)(out + (long long)r * FDIM + c) =
                    __floats2half2_rn(acc[im][in][0] * d0, acc[im][in][1] * d0);
            if (r + 8 < nrows)
                *(__half2*)(out + (long long)(r + 8) * FDIM + c) =
                    __floats2half2_rn(acc[im][in][2] * d1, acc[im][in][3] * d1);
        }
    }
}

// ---------------- aggregate: out[d] = b + dinv[d]*(yt[d] + sum yt[src]) -------
// warp per node; half-warp per edge; lane gathers uint4 (8 halves); pure adds.
template <typename TOut>
__global__ __launch_bounds__(256) void aggregate_kernel(
    const __half* __restrict__ yt, const int* __restrict__ rowptr,
    const int* __restrict__ cnt, const int* __restrict__ srcs,
    const float* __restrict__ dinv, const float* __restrict__ b,
    TOut* __restrict__ out, int n)
{
    int warp = (blockIdx.x * blockDim.x + threadIdx.x) >> 5;
    int lane = threadIdx.x & 31;
    if (warp >= n) return;
    int half_id = lane >> 4;
    int sub = lane & 15;

    float acc[8];
#pragma unroll
    for (int j = 0; j < 8; j++) acc[j] = 0.0f;

    int k0 = __ldg(rowptr + warp);
    int k1 = k0 + __ldg(cnt + warp);

#pragma unroll 8
    for (int k = k0 + half_id; k < k1; k += 2) {
        int s = __ldg(srcs + k);
        uint4 v = *(const uint4*)(yt + (long long)s * FDIM + sub * 8);
        float2 f0 = __half22float2(*(__half2*)&v.x);
        float2 f1 = __half22float2(*(__half2*)&v.y);
        float2 f2 = __half22float2(*(__half2*)&v.z);
        float2 f3 = __half22float2(*(__half2*)&v.w);
        acc[0] += f0.x; acc[1] += f0.y;
        acc[2] += f1.x; acc[3] += f1.y;
        acc[4] += f2.x; acc[5] += f2.y;
        acc[6] += f3.x; acc[7] += f3.y;
    }

    __syncwarp();
#pragma unroll
    for (int j = 0; j < 8; j++)
        acc[j] += __shfl_down_sync(0xffffffffu, acc[j], 16);

    if (half_id == 0) {
        float dc = __ldg(dinv + warp);
        uint4 s = *(const uint4*)(yt + (long long)warp * FDIM + sub * 8);
        float2 s0 = __half22float2(*(__half2*)&s.x);
        float2 s1 = __half22float2(*(__half2*)&s.y);
        float2 s2 = __half22float2(*(__half2*)&s.z);
        float2 s3 = __half22float2(*(__half2*)&s.w);
        float4 b0 = *(const float4*)(b + sub * 8);
        float4 b1 = *(const float4*)(b + sub * 8 + 4);
        float o[8];
        o[0] = fmaf(acc[0] + s0.x, dc, b0.x);
        o[1] = fmaf(acc[1] + s0.y, dc, b0.y);
        o[2] = fmaf(acc[2] + s1.x, dc, b0.z);
        o[3] = fmaf(acc[3] + s1.y, dc, b0.w);
        o[4] = fmaf(acc[4] + s2.x, dc, b1.x);
        o[5] = fmaf(acc[5] + s2.y, dc, b1.y);
        o[6] = fmaf(acc[6] + s3.x, dc, b1.z);
        o[7] = fmaf(acc[7] + s3.y, dc, b1.w);
        if constexpr (sizeof(TOut) == 4) {
            float* op = (float*)out + (long long)warp * FDIM + sub * 8;
            *(float4*)op       = make_float4(o[0], o[1], o[2], o[3]);
            *(float4*)(op + 4) = make_float4(o[4], o[5], o[6], o[7]);
        } else {
            __half* op = (__half*)out + (long long)warp * FDIM + sub * 8;
            ((__half2*)op)[0] = __floats2half2_rn(o[0], o[1]);
            ((__half2*)op)[1] = __floats2half2_rn(o[2], o[3]);
            ((__half2*)op)[2] = __floats2half2_rn(o[4], o[5]);
            ((__half2*)op)[3] = __floats2half2_rn(o[6], o[7]);
        }
    }
}

// ---------------- launch ----------------
extern "C" void kernel_launch(void* const* d_in, const int* in_sizes, int n_in,
                              void* d_out, int out_size)
{
    const float* node_feature = (const float*)d_in[0];
    const int*   edge_index   = (const int*)d_in[1];   // int32 (jax x64 disabled)
    const float* W1 = (const float*)d_in[2];
    const float* b1 = (const float*)d_in[3];
    const float* W2 = (const float*)d_in[4];
    const float* b2 = (const float*)d_in[5];
    float* out = (float*)d_out;

    int n = in_sizes[0] / FDIM;          // 100000
    int E = in_sizes[1] / 2;             // 1600000
    const int* rows = edge_index;
    const int* cols = edge_index + E;

    __half *yt, *h1;
    float* dinv;
    int *cnt, *rowptr, *cur, *srcs, *bsums;
    cudaGetSymbolAddress((void**)&yt,     g_yt);
    cudaGetSymbolAddress((void**)&h1,     g_h1);
    cudaGetSymbolAddress((void**)&dinv,   g_dinv);
    cudaGetSymbolAddress((void**)&cnt,    g_cnt);
    cudaGetSymbolAddress((void**)&rowptr, g_rowptr);
    cudaGetSymbolAddress((void**)&cur,    g_cur);
    cudaGetSymbolAddress((void**)&srcs,   g_srcs);
    cudaGetSymbolAddress((void**)&bsums,  g_bsums);

    int tb = 256;
    int nb_nodes = (n + tb - 1) / tb;
    int nb_edge4 = ((E >> 2) + tb - 1) / tb;
    int nb_gemm  = (n + MT - 1) / MT;
    int nb_scan  = (n + SCAN_BS - 1) / SCAN_BS;
    int nb_agg   = (n * 32 + tb - 1) / tb;

    // side stream + events (created per call, intentionally not destroyed:
    // destroying a capture-participating stream invalidates graph capture)
    cudaStream_t s_csr;
    cudaEvent_t ev_fork, ev_join;
    cudaStreamCreateWithFlags(&s_csr, cudaStreamNonBlocking);
    cudaEventCreateWithFlags(&ev_fork, cudaEventDisableTiming);
    cudaEventCreateWithFlags(&ev_join, cudaEventDisableTiming);

    // histogram + dinv on main (gemm1 epilogue needs dinv)
    cnt_zero_kernel<<<nb_nodes, tb>>>(cnt, n);
    hist_kernel<<<nb_edge4, tb>>>(cols, cnt, E);
    dinv_kernel<<<nb_nodes, tb>>>(cnt, dinv, n);

    // fork: scan + place on side stream, gemm1 on main
    cudaEventRecord(ev_fork, 0);
    cudaStreamWaitEvent(s_csr, ev_fork, 0);
    scan_block_kernel<<<nb_scan, SCAN_BS, 0, s_csr>>>(cnt, rowptr, bsums, n);
    scan_add_cursor_kernel<<<nb_scan, SCAN_BS, 0, s_csr>>>(rowptr, bsums, cur, n, nb_scan);
    place_kernel<<<nb_edge4, tb, 0, s_csr>>>(rows, cols, cur, srcs, E);
    cudaEventRecord(ev_join, s_csr);

    gemm_tc_kernel<float><<<nb_gemm, tb>>>(node_feature, W1, dinv, yt, n);

    // join; layer 1 aggregate -> h1 (fp16)
    cudaStreamWaitEvent(0, ev_join, 0);
    aggregate_kernel<__half><<<nb_agg, tb>>>(yt, rowptr, cnt, srcs, dinv, b1, h1, n);

    // layer 2
    gemm_tc_kernel<__half><<<nb_gemm, tb>>>(h1, W2, dinv, yt, n);
    aggregate_kernel<float><<<nb_agg, tb>>>(yt, rowptr, cnt, srcs, dinv, b2, out, n);
}